// round 14
// baseline (speedup 1.0000x reference)
#include <cuda_runtime.h>
#include <cuda_fp16.h>
#include <cstdint>

typedef long long ll;

// ============================ helpers ============================
__device__ __forceinline__ uint32_t smem_u32(const void* p) {
    uint32_t a;
    asm("{ .reg .u64 t; cvta.to.shared.u64 t, %1; cvt.u32.u64 %0, t; }" : "=r"(a) : "l"(p));
    return a;
}
#define SWZ(o) ((o) ^ (((o) >> 3) & 0x70))

__device__ __forceinline__ void cpa16(uint32_t dst, const void* src) {
    asm volatile("cp.async.cg.shared.global [%0], [%1], 16;" :: "r"(dst), "l"(src));
}
__device__ __forceinline__ void cpa_commit() {
    asm volatile("cp.async.commit_group;");
}
template <int N>
__device__ __forceinline__ void cpa_wait() {
    asm volatile("cp.async.wait_group %0;" :: "n"(N));
}
__device__ __forceinline__ void ldmx4(uint32_t* r, uint32_t addr) {
    asm volatile("ldmatrix.sync.aligned.m8n8.x4.shared.b16 {%0,%1,%2,%3}, [%4];"
                 : "=r"(r[0]), "=r"(r[1]), "=r"(r[2]), "=r"(r[3]) : "r"(addr));
}
__device__ __forceinline__ void mma16816(float* c, const uint32_t* a, const uint32_t* b) {
    asm volatile(
        "mma.sync.aligned.m16n8k16.row.col.f32.f16.f16.f32 "
        "{%0,%1,%2,%3}, {%4,%5,%6,%7}, {%8,%9}, {%0,%1,%2,%3};"
        : "+f"(c[0]), "+f"(c[1]), "+f"(c[2]), "+f"(c[3])
        : "r"(a[0]), "r"(a[1]), "r"(a[2]), "r"(a[3]), "r"(b[0]), "r"(b[1]));
}
__device__ __forceinline__ void split2(float v, __half& h, __half& l) {
    h = __float2half_rn(v);
    l = __float2half_rn(v - __half2float(h));
}
__device__ __forceinline__ uint32_t pack_h2(__half a, __half b) {
    __half2 t = __halves2half2(a, b);
    return *(uint32_t*)&t;
}

// ============================ scratch pool ============================
static constexpr size_t NX   = (size_t)4 * 4096 * 1024;
static constexpr size_t NW   = (size_t)1024 * 1024;
static constexpr size_t NATT = (size_t)4 * 16 * 4096 * 256;

static constexpr size_t o_xh  = 0;
static constexpr size_t o_xl  = o_xh  + NX;
static constexpr size_t o_qh  = o_xl  + NX;
static constexpr size_t o_ql  = o_qh  + NX;
static constexpr size_t o_kth = o_ql  + NX;   // K transposed split (b,1024,4096)
static constexpr size_t o_ktl = o_kth + NX;
static constexpr size_t o_vth = o_ktl + NX;   // V transposed split
static constexpr size_t o_vtl = o_vth + NX;
static constexpr size_t o_ohh = o_vtl + NX;
static constexpr size_t o_ohl = o_ohh + NX;
static constexpr size_t o_wqh = o_ohl + NX;
static constexpr size_t o_wql = o_wqh + NW;
static constexpr size_t o_wkh = o_wql + NW;
static constexpr size_t o_wkl = o_wkh + NW;
static constexpr size_t o_wvh = o_wkl + NW;
static constexpr size_t o_wvl = o_wvh + NW;
static constexpr size_t o_woh = o_wvl + NW;
static constexpr size_t o_wol = o_woh + NW;
static constexpr size_t o_eh  = o_wol + NW;
static constexpr size_t o_el  = o_eh  + NW;
static constexpr size_t o_fh  = o_el  + NW;
static constexpr size_t o_fl  = o_fh  + NW;
static constexpr size_t o_kph = o_fl  + NW;
static constexpr size_t o_kpl = o_kph + NW;
static constexpr size_t o_vph = o_kpl + NW;
static constexpr size_t o_vpl = o_vph + NW;
static constexpr size_t o_st  = o_vpl + NW;   // softmax stats: 262144 float2 (1MB region is enough)
static constexpr size_t POOL_ELTS = o_st + NATT;  // keep pool size (stats live in old attn region)

__device__ uint4 g_pool4[(POOL_ELTS * 2 + 15) / 16];

// ============================ convert: fp32 -> split fp16 ============================
__global__ __launch_bounds__(256) void convert_split(
    const float* __restrict__ src, __half* __restrict__ H,
    __half* __restrict__ L, int n4)
{
    int i = blockIdx.x * 256 + threadIdx.x;
    if (i >= n4) return;
    float4 v = ((const float4*)src)[i];
    __half h0, l0, h1, l1, h2, l2, h3, l3;
    split2(v.x, h0, l0); split2(v.y, h1, l1);
    split2(v.z, h2, l2); split2(v.w, h3, l3);
    ((uint2*)H)[i] = make_uint2(pack_h2(h0, h1), pack_h2(h2, h3));
    ((uint2*)L)[i] = make_uint2(pack_h2(l0, l1), pack_h2(l2, l3));
}

struct P6 { const float* s[6]; __half* h[6]; __half* l[6]; };
__global__ __launch_bounds__(256) void convert6(P6 p, int n4)
{
    const int z = blockIdx.z;
    const float* src = p.s[z];
    __half* H = p.h[z];
    __half* L = p.l[z];
    int i = blockIdx.x * 256 + threadIdx.x;
    if (i >= n4) return;
    float4 v = ((const float4*)src)[i];
    __half h0, l0, h1, l1, h2, l2, h3, l3;
    split2(v.x, h0, l0); split2(v.y, h1, l1);
    split2(v.z, h2, l2); split2(v.w, h3, l3);
    ((uint2*)H)[i] = make_uint2(pack_h2(h0, h1), pack_h2(h2, h3));
    ((uint2*)L)[i] = make_uint2(pack_h2(l0, l1), pack_h2(l2, l3));
}

// ============================ softmax stats: per-row max & 1/sum ============================
// Same reduction math/order as the old softmax kernel -> bit-identical mx and sum.
__global__ __launch_bounds__(128) void softmax_stats(
    const float* __restrict__ s, float2* __restrict__ st)
{
    const int row = blockIdx.x * 4 + (threadIdx.x >> 5);
    const int lane = threadIdx.x & 31;
    const float* sp = s + (ll)row * 256 + lane * 8;
    float4 a = *(const float4*)sp;
    float4 b = *(const float4*)(sp + 4);
    float v[8] = {a.x, a.y, a.z, a.w, b.x, b.y, b.z, b.w};
    float mx = -3.4e38f;
#pragma unroll
    for (int i = 0; i < 8; i++) mx = fmaxf(mx, v[i]);
#pragma unroll
    for (int o = 16; o > 0; o >>= 1) mx = fmaxf(mx, __shfl_xor_sync(0xffffffffu, mx, o));
    float sum = 0.f;
#pragma unroll
    for (int i = 0; i < 8; i++) { v[i] = __expf(v[i] - mx); sum += v[i]; }
#pragma unroll
    for (int o = 16; o > 0; o >>= 1) sum += __shfl_xor_sync(0xffffffffu, sum, o);
    if (lane == 0) st[row] = make_float2(mx, 1.0f / sum);
}

// ============================ split-fp16 GEMM: 128 thr, tile 128x64x64, 2 CTAs/SM ============================
// (validated R13 config)
template <bool OUTF, bool OUTS, bool OUTT>
__global__ __launch_bounds__(128, 2) void gemm_mma(
    const __half* __restrict__ Ah, const __half* __restrict__ Al,
    const __half* __restrict__ Bh, const __half* __restrict__ Bl,
    const float* __restrict__ bias,
    float* __restrict__ Cf, __half* __restrict__ Ch, __half* __restrict__ Cl,
    int K, int lda, int ldb, int ldc,
    ll sAo, ll sAi, ll sBo, ll sBi, ll sCo, ll sCi, int zInner, float alpha)
{
    extern __shared__ char dsm[];
    constexpr int TA = 128 * 128;
    constexpr int TBb = 64 * 128;
    constexpr int STRIDE = 2 * TA + 2 * TBb;

    const int zo = blockIdx.z / zInner, zi = blockIdx.z - zo * zInner;
    Ah += zo * sAo + zi * sAi;  Al += zo * sAo + zi * sAi;
    Bh += zo * sBo + zi * sBi;  Bl += zo * sBo + zi * sBi;
    float* Cfz = OUTF ? (Cf + zo * sCo + zi * sCi) : nullptr;
    __half* Chz = (OUTS || OUTT) ? (Ch + (OUTT ? 0 : zo * sCo + zi * sCi)) : nullptr;
    __half* Clz = (OUTS || OUTT) ? (Cl + (OUTT ? 0 : zo * sCo + zi * sCi)) : nullptr;

    const int m0 = blockIdx.y * 128;
    const int n0 = blockIdx.x * 64;
    const int tid = threadIdx.x;
    const uint32_t sb = smem_u32(dsm);

    auto load_chunk = [&](int c) {
        const int buf = c & 1;
        const uint32_t bo = sb + buf * STRIDE;
        const ll kc = (ll)c * 64;
#pragma unroll
        for (int it = 0; it < 8; ++it) {
            const int u = tid + it * 128;
            const int row = u >> 3, c16 = u & 7;
            const uint32_t so = SWZ((uint32_t)(row * 128 + c16 * 16));
            const ll g = (ll)(m0 + row) * lda + kc + c16 * 8;
            cpa16(bo + so, Ah + g);
            cpa16(bo + TA + so, Al + g);
        }
#pragma unroll
        for (int it = 0; it < 4; ++it) {
            const int u = tid + it * 128;
            const int row = u >> 3, c16 = u & 7;
            const uint32_t so = SWZ((uint32_t)(row * 128 + c16 * 16));
            const ll g = (ll)(n0 + row) * ldb + kc + c16 * 8;
            cpa16(bo + 2 * TA + so, Bh + g);
            cpa16(bo + 2 * TA + TBb + so, Bl + g);
        }
        cpa_commit();
    };

    const int wid = tid >> 5, lane = tid & 31;
    const int m0w = wid * 32;
    const int lrow = lane & 15, lcol = lane >> 4;

    float acc[2][8][4];
#pragma unroll
    for (int i = 0; i < 2; i++)
#pragma unroll
        for (int j = 0; j < 8; j++)
#pragma unroll
            for (int q = 0; q < 4; q++) acc[i][j][q] = 0.f;

    const int nC = K >> 6;
    load_chunk(0);

    for (int c = 0; c < nC; ++c) {
        if (c + 1 < nC) { load_chunk(c + 1); cpa_wait<1>(); }
        else           { cpa_wait<0>(); }
        __syncthreads();

        const int buf = c & 1;
        const uint32_t As_h = sb + buf * STRIDE;
        const uint32_t As_l = As_h + TA;
        const uint32_t Bs_h = As_h + 2 * TA;
        const uint32_t Bs_l = Bs_h + TBb;

#pragma unroll
        for (int k16 = 0; k16 < 4; ++k16) {
            const uint32_t kb = k16 * 32;
            uint32_t ah[2][4], al[2][4];
#pragma unroll
            for (int i = 0; i < 2; ++i) {
                const uint32_t off = SWZ((uint32_t)((m0w + i * 16 + lrow) * 128) + kb + lcol * 16);
                ldmx4(ah[i], As_h + off);
                ldmx4(al[i], As_l + off);
            }
            uint32_t bh[8][2], bl[8][2];
#pragma unroll
            for (int p = 0; p < 4; ++p) {
                const uint32_t off = SWZ((uint32_t)((p * 16 + lrow) * 128) + kb + lcol * 16);
                uint32_t r[4];
                ldmx4(r, Bs_h + off);
                bh[2 * p][0] = r[0]; bh[2 * p][1] = r[2];
                bh[2 * p + 1][0] = r[1]; bh[2 * p + 1][1] = r[3];
                ldmx4(r, Bs_l + off);
                bl[2 * p][0] = r[0]; bl[2 * p][1] = r[2];
                bl[2 * p + 1][0] = r[1]; bl[2 * p + 1][1] = r[3];
            }
#pragma unroll
            for (int i = 0; i < 2; ++i)
#pragma unroll
                for (int j = 0; j < 8; ++j) {
                    mma16816(acc[i][j], ah[i], bh[j]);
                    mma16816(acc[i][j], ah[i], bl[j]);
                    mma16816(acc[i][j], al[i], bh[j]);
                }
        }
        __syncthreads();
    }

    const int gID = lane >> 2;
    const int tc2 = (lane & 3) * 2;

    if (OUTT) {
        constexpr int PADC = 66;
        __half* SH = (__half*)dsm;
        __half* SL = SH + 128 * PADC;
#pragma unroll
        for (int i = 0; i < 2; ++i) {
            const int r0l = m0w + i * 16 + gID;
#pragma unroll
            for (int j = 0; j < 8; ++j) {
                const int cl = j * 8 + tc2;
                float c0 = acc[i][j][0] * alpha, c1 = acc[i][j][1] * alpha;
                float c2 = acc[i][j][2] * alpha, c3 = acc[i][j][3] * alpha;
                if (bias) {
                    const float b0 = bias[n0 + cl], b1 = bias[n0 + cl + 1];
                    c0 += b0; c1 += b1; c2 += b0; c3 += b1;
                }
                __half h, l;
                split2(c0, h, l); SH[r0l * PADC + cl] = h;       SL[r0l * PADC + cl] = l;
                split2(c1, h, l); SH[r0l * PADC + cl + 1] = h;   SL[r0l * PADC + cl + 1] = l;
                split2(c2, h, l); SH[(r0l + 8) * PADC + cl] = h; SL[(r0l + 8) * PADC + cl] = l;
                split2(c3, h, l); SH[(r0l + 8) * PADC + cl + 1] = h; SL[(r0l + 8) * PADC + cl + 1] = l;
            }
        }
        __syncthreads();
        const int bT = m0 >> 12;
        const int t0 = m0 & 4095;
        const int ch = tid & 63;
        const int hf = tid >> 6;
        const ll dbase = (ll)bT * 1024 * 4096 + (ll)(n0 + ch) * 4096 + t0 + hf * 64;
#pragma unroll
        for (int s8 = 0; s8 < 8; ++s8) {
            __half th[8], tl[8];
#pragma unroll
            for (int e = 0; e < 8; ++e) {
                const int tok = hf * 64 + s8 * 8 + e;
                th[e] = SH[tok * PADC + ch];
                tl[e] = SL[tok * PADC + ch];
            }
            *(uint4*)(Chz + dbase + s8 * 8) = *(uint4*)th;
            *(uint4*)(Clz + dbase + s8 * 8) = *(uint4*)tl;
        }
        return;
    }

#pragma unroll
    for (int i = 0; i < 2; ++i) {
        const int rA = m0 + m0w + i * 16 + gID;
        const int rB = rA + 8;
#pragma unroll
        for (int j = 0; j < 8; ++j) {
            const int col = n0 + j * 8 + tc2;
            float c0 = acc[i][j][0] * alpha, c1 = acc[i][j][1] * alpha;
            float c2 = acc[i][j][2] * alpha, c3 = acc[i][j][3] * alpha;
            if (bias) {
                const float b0 = bias[col], b1 = bias[col + 1];
                c0 += b0; c1 += b1; c2 += b0; c3 += b1;
            }
            if (OUTF) {
                *(float2*)(Cfz + (ll)rA * ldc + col) = make_float2(c0, c1);
                *(float2*)(Cfz + (ll)rB * ldc + col) = make_float2(c2, c3);
            }
            if (OUTS) {
                __half h0, l0, h1, l1;
                split2(c0, h0, l0); split2(c1, h1, l1);
                *(uint32_t*)(Chz + (ll)rA * ldc + col) = pack_h2(h0, h1);
                *(uint32_t*)(Clz + (ll)rA * ldc + col) = pack_h2(l0, l1);
                split2(c2, h0, l0); split2(c3, h1, l1);
                *(uint32_t*)(Chz + (ll)rB * ldc + col) = pack_h2(h0, h1);
                *(uint32_t*)(Clz + (ll)rB * ldc + col) = pack_h2(l0, l1);
            }
        }
    }
}

// ============================ fused softmax+AV kernel ============================
// grid (1, 32, 64): y = token tile (128 tokens), z = (b*16+h).
// A = softmax(scores[z]) tile 128x256 built on the fly (split fp16, SW128 smem);
// B = VpT[b, h*64:(h+1)*64, :] (64 rows x 256, split fp16);
// C = outh[b, tok, h*64:(h+1)*64] split fp16, ldc=1024. K=256 (4 chunks).
__global__ __launch_bounds__(128, 2) void av_fused(
    const float* __restrict__ scores, const float2* __restrict__ stats,
    const __half* __restrict__ VpTh, const __half* __restrict__ VpTl,
    __half* __restrict__ Ch, __half* __restrict__ Cl)
{
    extern __shared__ char dsm[];
    constexpr int TAH = 128 * 128;     // A hi: 128 rows x 128B (16 KB); lo follows
    constexpr int TBH = 64 * 128;      // B hi per stage (8 KB); lo follows
    // layout: [A hi 16K][A lo 16K][B stage0 hi 8K|lo 8K][B stage1 hi 8K|lo 8K] = 64 KB

    const int z = blockIdx.z;          // (b,h)
    const int b = z >> 4, h = z & 15;
    const int t0g = blockIdx.y * 128;  // token base
    const int tid = threadIdx.x;
    const uint32_t sb = smem_u32(dsm);
    const uint32_t aH = sb, aL = sb + TAH;
    const uint32_t bBase = sb + 2 * TAH;

    const float* sc = scores + ((ll)z * 4096 + t0g) * 256;
    const float2 st = stats[(ll)z * 4096 + t0g + tid];   // row = tid
    const float mx = st.x, inv = st.y;
    const __half* Bh = VpTh + (ll)b * 1024 * 256 + (ll)h * 64 * 256;
    const __half* Bl = VpTl + (ll)b * 1024 * 256 + (ll)h * 64 * 256;
    __half* Chz = Ch + (ll)b * 4096 * 1024 + (ll)t0g * 1024 + h * 64;
    __half* Clz = Cl + (ll)b * 4096 * 1024 + (ll)t0g * 1024 + h * 64;

    auto load_B = [&](int c) {
        const uint32_t bo = bBase + (c & 1) * 2 * TBH;
        const ll kc = (ll)c * 64;
#pragma unroll
        for (int it = 0; it < 4; ++it) {
            const int u = tid + it * 128;
            const int row = u >> 3, c16 = u & 7;
            const uint32_t so = SWZ((uint32_t)(row * 128 + c16 * 16));
            const ll g = (ll)row * 256 + kc + c16 * 8;
            cpa16(bo + so, Bh + g);
            cpa16(bo + TBH + so, Bl + g);
        }
        cpa_commit();
    };

    // convert prefetched fp32 scores row-chunk -> softmax -> split fp16 -> STS
    auto convert_sts = [&](const float4* ar) {
#pragma unroll
        for (int j = 0; j < 8; ++j) {           // 8 groups of 8 values
            float v[8];
            const float4 p0 = ar[2 * j], p1 = ar[2 * j + 1];
            v[0] = p0.x; v[1] = p0.y; v[2] = p0.z; v[3] = p0.w;
            v[4] = p1.x; v[5] = p1.y; v[6] = p1.z; v[7] = p1.w;
            __half hh[8], llw[8];
#pragma unroll
            for (int e = 0; e < 8; ++e) {
                const float a = __expf(v[e] - mx) * inv;
                split2(a, hh[e], llw[e]);
            }
            const uint32_t so = SWZ((uint32_t)(tid * 128 + j * 16));
            *(uint4*)(dsm + (aH - sb) + so) = *(const uint4*)hh;
            *(uint4*)(dsm + (aL - sb) + so) = *(const uint4*)llw;
        }
    };

    const int wid = tid >> 5, lane = tid & 31;
    const int m0w = wid * 32;
    const int lrow = lane & 15, lcol = lane >> 4;

    float acc[2][8][4];
#pragma unroll
    for (int i = 0; i < 2; i++)
#pragma unroll
        for (int j = 0; j < 8; j++)
#pragma unroll
            for (int q = 0; q < 4; q++) acc[i][j][q] = 0.f;

    // prologue: B chunk0 async; A chunk0 regs
    load_B(0);
    float4 ar[16], ar2[16];
    const float4* scf = (const float4*)(sc + (ll)tid * 256);
#pragma unroll
    for (int i = 0; i < 16; ++i) ar[i] = scf[i];

    for (int c = 0; c < 4; ++c) {
        if (c < 3) load_B(c + 1);
        convert_sts(ar);                        // STS chunk c into A buf
        if (c < 3) {
#pragma unroll
            for (int i = 0; i < 16; ++i) ar2[i] = scf[(c + 1) * 16 + i];
        }
        if (c < 3) cpa_wait<1>(); else cpa_wait<0>();
        __syncthreads();                        // A STS + B(c) visible

        const uint32_t Bs_h = bBase + (c & 1) * 2 * TBH;
        const uint32_t Bs_l = Bs_h + TBH;
#pragma unroll
        for (int k16 = 0; k16 < 4; ++k16) {
            const uint32_t kb = k16 * 32;
            uint32_t ah[2][4], al[2][4];
#pragma unroll
            for (int i = 0; i < 2; ++i) {
                const uint32_t off = SWZ((uint32_t)((m0w + i * 16 + lrow) * 128) + kb + lcol * 16);
                ldmx4(ah[i], aH + off);
                ldmx4(al[i], aL + off);
            }
            uint32_t bh[8][2], bl[8][2];
#pragma unroll
            for (int p = 0; p < 4; ++p) {
                const uint32_t off = SWZ((uint32_t)((p * 16 + lrow) * 128) + kb + lcol * 16);
                uint32_t r[4];
                ldmx4(r, Bs_h + off);
                bh[2 * p][0] = r[0]; bh[2 * p][1] = r[2];
                bh[2 * p + 1][0] = r[1]; bh[2 * p + 1][1] = r[3];
                ldmx4(r, Bs_l + off);
                bl[2 * p][0] = r[0]; bl[2 * p][1] = r[2];
                bl[2 * p + 1][0] = r[1]; bl[2 * p + 1][1] = r[3];
            }
#pragma unroll
            for (int i = 0; i < 2; ++i)
#pragma unroll
                for (int j = 0; j < 8; ++j) {
                    mma16816(acc[i][j], ah[i], bh[j]);
                    mma16816(acc[i][j], ah[i], bl[j]);
                    mma16816(acc[i][j], al[i], bh[j]);
                }
        }
        __syncthreads();                        // all reads of A buf done
#pragma unroll
        for (int i = 0; i < 16; ++i) ar[i] = ar2[i];
    }

    // ---- epilogue: split fp16 out (ldc=1024) ----
    const int gID = lane >> 2;
    const int tc2 = (lane & 3) * 2;
#pragma unroll
    for (int i = 0; i < 2; ++i) {
        const int rA = m0w + i * 16 + gID;
        const int rB = rA + 8;
#pragma unroll
        for (int j = 0; j < 8; ++j) {
            const int col = j * 8 + tc2;
            const float c0 = acc[i][j][0], c1 = acc[i][j][1];
            const float c2 = acc[i][j][2], c3 = acc[i][j][3];
            __half h0, l0, h1, l1;
            split2(c0, h0, l0); split2(c1, h1, l1);
            *(uint32_t*)(Chz + (ll)rA * 1024 + col) = pack_h2(h0, h1);
            *(uint32_t*)(Clz + (ll)rA * 1024 + col) = pack_h2(l0, l1);
            split2(c2, h0, l0); split2(c3, h1, l1);
            *(uint32_t*)(Chz + (ll)rB * 1024 + col) = pack_h2(h0, h1);
            *(uint32_t*)(Clz + (ll)rB * 1024 + col) = pack_h2(l0, l1);
        }
    }
}

// ============================ host launch ============================
extern "C" void kernel_launch(void* const* d_in, const int* in_sizes, int n_in,
                              void* d_out, int out_size)
{
    const float* x  = (const float*)d_in[0];
    const float* Wq = (const float*)d_in[1];
    const float* bq = (const float*)d_in[2];
    const float* Wk = (const float*)d_in[3];
    const float* bk = (const float*)d_in[4];
    const float* Wv = (const float*)d_in[5];
    const float* bv = (const float*)d_in[6];
    const float* E  = (const float*)d_in[7];
    const float* F  = (const float*)d_in[8];
    const float* Wo = (const float*)d_in[9];
    const float* bo = (const float*)d_in[10];

    float* out    = (float*)d_out;                 // (4,4096,1024)
    float* scores = out + (ll)4 * 4096 * 1024;     // (4,16,4096,256)

    __half* P;
    cudaGetSymbolAddress((void**)&P, g_pool4);
#define PP(o) (P + (o))

    auto G1  = gemm_mma<false, true,  false>;  // split fp16 out
    auto G1T = gemm_mma<false, false, true>;   // split fp16 out, transposed
    auto G2  = gemm_mma<true,  false, false>;  // fp32 out
    const int DYN = 2 * (2 * 128 * 128 + 2 * 64 * 128);  // 98304
    const int DYNAV = 2 * 128 * 128 + 2 * 2 * 64 * 128;  // 65536
    cudaFuncSetAttribute(G1,  cudaFuncAttributeMaxDynamicSharedMemorySize, DYN);
    cudaFuncSetAttribute(G1T, cudaFuncAttributeMaxDynamicSharedMemorySize, DYN);
    cudaFuncSetAttribute(G2,  cudaFuncAttributeMaxDynamicSharedMemorySize, DYN);
    cudaFuncSetAttribute(av_fused, cudaFuncAttributeMaxDynamicSharedMemorySize, DYNAV);

    // 1) converts (2 launches)
    convert_split<<<(int)(NX / 4 / 256), 256>>>(x, PP(o_xh), PP(o_xl), (int)(NX / 4));
    {
        P6 p;
        p.s[0] = Wq; p.h[0] = PP(o_wqh); p.l[0] = PP(o_wql);
        p.s[1] = Wk; p.h[1] = PP(o_wkh); p.l[1] = PP(o_wkl);
        p.s[2] = Wv; p.h[2] = PP(o_wvh); p.l[2] = PP(o_wvl);
        p.s[3] = Wo; p.h[3] = PP(o_woh); p.l[3] = PP(o_wol);
        p.s[4] = E;  p.h[4] = PP(o_eh);  p.l[4] = PP(o_el);
        p.s[5] = F;  p.h[5] = PP(o_fh);  p.l[5] = PP(o_fl);
        convert6<<<dim3((int)(NW / 4 / 256), 1, 6), 256>>>(p, (int)(NW / 4));
    }

    // 2) projections: Q normal; K,V write transposed split directly
    {
        dim3 g(16, 128, 1);
        G1<<<g, 128, DYN>>>(PP(o_xh), PP(o_xl), PP(o_wqh), PP(o_wql), bq,
                            nullptr, PP(o_qh), PP(o_ql),
                            1024, 1024, 1024, 1024, 0, 0, 0, 0, 0, 0, 1, 1.0f);
        G1T<<<g, 128, DYN>>>(PP(o_xh), PP(o_xl), PP(o_wkh), PP(o_wkl), bk,
                             nullptr, PP(o_kth), PP(o_ktl),
                             1024, 1024, 1024, 0, 0, 0, 0, 0, 0, 0, 1, 1.0f);
        G1T<<<g, 128, DYN>>>(PP(o_xh), PP(o_xl), PP(o_wvh), PP(o_wvl), bv,
                             nullptr, PP(o_vth), PP(o_vtl),
                             1024, 1024, 1024, 0, 0, 0, 0, 0, 0, 0, 1, 1.0f);
    }

    // 3) Kp[b](256x1024) = E * Kt[b]^T
    G1<<<dim3(16, 2, 4), 128, DYN>>>(PP(o_eh), PP(o_el), PP(o_kth), PP(o_ktl), nullptr,
                                     nullptr, PP(o_kph), PP(o_kpl),
                                     4096, 4096, 4096, 1024,
                                     0, 0, (ll)1024 * 4096, 0, (ll)256 * 1024, 0, 1, 1.0f);
    // 4) VpT[b](1024x256) = Vt[b] * F^T
    G1<<<dim3(4, 8, 4), 128, DYN>>>(PP(o_vth), PP(o_vtl), PP(o_fh), PP(o_fl), nullptr,
                                    nullptr, PP(o_vph), PP(o_vpl),
                                    4096, 4096, 4096, 256,
                                    (ll)1024 * 4096, 0, 0, 0, (ll)1024 * 256, 0, 1, 1.0f);

    // 5) scores[b,h](4096x256) = Q_h(4096x64) * Kp_h^T / 8  -> fp32 into d_out
    G2<<<dim3(4, 32, 64), 128, DYN>>>(PP(o_qh), PP(o_ql), PP(o_kph), PP(o_kpl), nullptr,
                                      scores, nullptr, nullptr,
                                      64, 1024, 1024, 256,
                                      (ll)4096 * 1024, 64, (ll)256 * 1024, 64,
                                      (ll)16 * 4096 * 256, (ll)4096 * 256, 16, 0.125f);

    // 6) softmax stats (per-row max + 1/sum, 2MB)
    softmax_stats<<<(4 * 16 * 4096) / 4, 128>>>(scores, (float2*)PP(o_st));

    // 7) fused softmax+AV: outh split directly from scores + stats
    av_fused<<<dim3(1, 32, 64), 128, DYNAV>>>(scores, (const float2*)PP(o_st),
                                              PP(o_vph), PP(o_vpl),
                                              PP(o_ohh), PP(o_ohl));

    // 8) out = outh * Wo^T + bo  (fp32 into d_out)
    G2<<<dim3(16, 128, 1), 128, DYN>>>(PP(o_ohh), PP(o_ohl), PP(o_woh), PP(o_wol), bo,
                                       out, nullptr, nullptr,
                                       1024, 1024, 1024, 1024,
                                       0, 0, 0, 0, 0, 0, 1, 1.0f);
#undef PP
}

// round 15
// speedup vs baseline: 1.0110x; 1.0110x over previous
#include <cuda_runtime.h>
#include <cuda_fp16.h>
#include <cstdint>

typedef long long ll;

// ============================ helpers ============================
__device__ __forceinline__ uint32_t smem_u32(const void* p) {
    uint32_t a;
    asm("{ .reg .u64 t; cvta.to.shared.u64 t, %1; cvt.u32.u64 %0, t; }" : "=r"(a) : "l"(p));
    return a;
}
#define SWZ(o) ((o) ^ (((o) >> 3) & 0x70))

__device__ __forceinline__ void cpa16(uint32_t dst, const void* src) {
    asm volatile("cp.async.cg.shared.global [%0], [%1], 16;" :: "r"(dst), "l"(src));
}
__device__ __forceinline__ void cpa_commit() {
    asm volatile("cp.async.commit_group;");
}
template <int N>
__device__ __forceinline__ void cpa_wait() {
    asm volatile("cp.async.wait_group %0;" :: "n"(N));
}
__device__ __forceinline__ void ldmx4(uint32_t* r, uint32_t addr) {
    asm volatile("ldmatrix.sync.aligned.m8n8.x4.shared.b16 {%0,%1,%2,%3}, [%4];"
                 : "=r"(r[0]), "=r"(r[1]), "=r"(r[2]), "=r"(r[3]) : "r"(addr));
}
__device__ __forceinline__ void mma16816(float* c, const uint32_t* a, const uint32_t* b) {
    asm volatile(
        "mma.sync.aligned.m16n8k16.row.col.f32.f16.f16.f32 "
        "{%0,%1,%2,%3}, {%4,%5,%6,%7}, {%8,%9}, {%0,%1,%2,%3};"
        : "+f"(c[0]), "+f"(c[1]), "+f"(c[2]), "+f"(c[3])
        : "r"(a[0]), "r"(a[1]), "r"(a[2]), "r"(a[3]), "r"(b[0]), "r"(b[1]));
}
__device__ __forceinline__ void split2(float v, __half& h, __half& l) {
    h = __float2half_rn(v);
    l = __float2half_rn(v - __half2float(h));
}
__device__ __forceinline__ uint32_t pack_h2(__half a, __half b) {
    __half2 t = __halves2half2(a, b);
    return *(uint32_t*)&t;
}

// ============================ scratch pool ============================
static constexpr size_t NX   = (size_t)4 * 4096 * 1024;
static constexpr size_t NW   = (size_t)1024 * 1024;
static constexpr size_t NATT = (size_t)4 * 16 * 4096 * 256;

static constexpr size_t o_xh  = 0;
static constexpr size_t o_xl  = o_xh  + NX;
static constexpr size_t o_qh  = o_xl  + NX;
static constexpr size_t o_ql  = o_qh  + NX;
static constexpr size_t o_kth = o_ql  + NX;
static constexpr size_t o_ktl = o_kth + NX;
static constexpr size_t o_vth = o_ktl + NX;
static constexpr size_t o_vtl = o_vth + NX;
static constexpr size_t o_ohh = o_vtl + NX;
static constexpr size_t o_ohl = o_ohh + NX;
static constexpr size_t o_wqh = o_ohl + NX;
static constexpr size_t o_wql = o_wqh + NW;
static constexpr size_t o_wkh = o_wql + NW;
static constexpr size_t o_wkl = o_wkh + NW;
static constexpr size_t o_wvh = o_wkl + NW;
static constexpr size_t o_wvl = o_wvh + NW;
static constexpr size_t o_woh = o_wvl + NW;
static constexpr size_t o_wol = o_woh + NW;
static constexpr size_t o_eh  = o_wol + NW;
static constexpr size_t o_el  = o_eh  + NW;
static constexpr size_t o_fh  = o_el  + NW;
static constexpr size_t o_fl  = o_fh  + NW;
static constexpr size_t o_kph = o_fl  + NW;
static constexpr size_t o_kpl = o_kph + NW;
static constexpr size_t o_vph = o_kpl + NW;
static constexpr size_t o_vpl = o_vph + NW;
static constexpr size_t o_st  = o_vpl + NW;        // stats: 262144 float2 = 8 MB = 4M halves
static constexpr size_t o_pk  = o_st + 4194304;    // Kp fp32 partials: 2 x 1M floats = 4M halves
static constexpr size_t o_pv  = o_pk + 4194304;    // Vp fp32 partials: 2 x 1M floats = 4M halves
static constexpr size_t POOL_ELTS = o_st + NATT;   // plenty

__device__ uint4 g_pool4[(POOL_ELTS * 2 + 15) / 16];

// ============================ convert: fp32 -> split fp16 ============================
__global__ __launch_bounds__(256) void convert_split(
    const float* __restrict__ src, __half* __restrict__ H,
    __half* __restrict__ L, int n4)
{
    int i = blockIdx.x * 256 + threadIdx.x;
    if (i >= n4) return;
    float4 v = ((const float4*)src)[i];
    __half h0, l0, h1, l1, h2, l2, h3, l3;
    split2(v.x, h0, l0); split2(v.y, h1, l1);
    split2(v.z, h2, l2); split2(v.w, h3, l3);
    ((uint2*)H)[i] = make_uint2(pack_h2(h0, h1), pack_h2(h2, h3));
    ((uint2*)L)[i] = make_uint2(pack_h2(l0, l1), pack_h2(l2, l3));
}

// add two fp32 partials, emit split fp16
__global__ __launch_bounds__(256) void add_split(
    const float* __restrict__ P0, const float* __restrict__ P1,
    __half* __restrict__ H, __half* __restrict__ L, int n4)
{
    int i = blockIdx.x * 256 + threadIdx.x;
    if (i >= n4) return;
    float4 a = ((const float4*)P0)[i];
    float4 b = ((const float4*)P1)[i];
    a.x += b.x; a.y += b.y; a.z += b.z; a.w += b.w;
    __half h0, l0, h1, l1, h2, l2, h3, l3;
    split2(a.x, h0, l0); split2(a.y, h1, l1);
    split2(a.z, h2, l2); split2(a.w, h3, l3);
    ((uint2*)H)[i] = make_uint2(pack_h2(h0, h1), pack_h2(h2, h3));
    ((uint2*)L)[i] = make_uint2(pack_h2(l0, l1), pack_h2(l2, l3));
}

struct P6 { const float* s[6]; __half* h[6]; __half* l[6]; };
__global__ __launch_bounds__(256) void convert6(P6 p, int n4)
{
    const int z = blockIdx.z;
    const float* src = p.s[z];
    __half* H = p.h[z];
    __half* L = p.l[z];
    int i = blockIdx.x * 256 + threadIdx.x;
    if (i >= n4) return;
    float4 v = ((const float4*)src)[i];
    __half h0, l0, h1, l1, h2, l2, h3, l3;
    split2(v.x, h0, l0); split2(v.y, h1, l1);
    split2(v.z, h2, l2); split2(v.w, h3, l3);
    ((uint2*)H)[i] = make_uint2(pack_h2(h0, h1), pack_h2(h2, h3));
    ((uint2*)L)[i] = make_uint2(pack_h2(l0, l1), pack_h2(l2, l3));
}

// ============================ softmax stats: per-row max & 1/sum ============================
__global__ __launch_bounds__(128) void softmax_stats(
    const float* __restrict__ s, float2* __restrict__ st)
{
    const int row = blockIdx.x * 4 + (threadIdx.x >> 5);
    const int lane = threadIdx.x & 31;
    const float* sp = s + (ll)row * 256 + lane * 8;
    float4 a = *(const float4*)sp;
    float4 b = *(const float4*)(sp + 4);
    float v[8] = {a.x, a.y, a.z, a.w, b.x, b.y, b.z, b.w};
    float mx = -3.4e38f;
#pragma unroll
    for (int i = 0; i < 8; i++) mx = fmaxf(mx, v[i]);
#pragma unroll
    for (int o = 16; o > 0; o >>= 1) mx = fmaxf(mx, __shfl_xor_sync(0xffffffffu, mx, o));
    float sum = 0.f;
#pragma unroll
    for (int i = 0; i < 8; i++) { v[i] = __expf(v[i] - mx); sum += v[i]; }
#pragma unroll
    for (int o = 16; o > 0; o >>= 1) sum += __shfl_xor_sync(0xffffffffu, sum, o);
    if (lane == 0) st[row] = make_float2(mx, 1.0f / sum);
}

// ============================ split-fp16 GEMM: 128 thr, tile 128x64x64, 2 CTAs/SM ============================
template <bool OUTF, bool OUTS, bool OUTT>
__global__ __launch_bounds__(128, 2) void gemm_mma(
    const __half* __restrict__ Ah, const __half* __restrict__ Al,
    const __half* __restrict__ Bh, const __half* __restrict__ Bl,
    const float* __restrict__ bias,
    float* __restrict__ Cf, __half* __restrict__ Ch, __half* __restrict__ Cl,
    int K, int lda, int ldb, int ldc,
    ll sAo, ll sAi, ll sBo, ll sBi, ll sCo, ll sCi, int zInner, float alpha)
{
    extern __shared__ char dsm[];
    constexpr int TA = 128 * 128;
    constexpr int TBb = 64 * 128;
    constexpr int STRIDE = 2 * TA + 2 * TBb;

    const int zo = blockIdx.z / zInner, zi = blockIdx.z - zo * zInner;
    Ah += zo * sAo + zi * sAi;  Al += zo * sAo + zi * sAi;
    Bh += zo * sBo + zi * sBi;  Bl += zo * sBo + zi * sBi;
    float* Cfz = OUTF ? (Cf + zo * sCo + zi * sCi) : nullptr;
    __half* Chz = (OUTS || OUTT) ? (Ch + (OUTT ? 0 : zo * sCo + zi * sCi)) : nullptr;
    __half* Clz = (OUTS || OUTT) ? (Cl + (OUTT ? 0 : zo * sCo + zi * sCi)) : nullptr;

    const int m0 = blockIdx.y * 128;
    const int n0 = blockIdx.x * 64;
    const int tid = threadIdx.x;
    const uint32_t sb = smem_u32(dsm);

    auto load_chunk = [&](int c) {
        const int buf = c & 1;
        const uint32_t bo = sb + buf * STRIDE;
        const ll kc = (ll)c * 64;
#pragma unroll
        for (int it = 0; it < 8; ++it) {
            const int u = tid + it * 128;
            const int row = u >> 3, c16 = u & 7;
            const uint32_t so = SWZ((uint32_t)(row * 128 + c16 * 16));
            const ll g = (ll)(m0 + row) * lda + kc + c16 * 8;
            cpa16(bo + so, Ah + g);
            cpa16(bo + TA + so, Al + g);
        }
#pragma unroll
        for (int it = 0; it < 4; ++it) {
            const int u = tid + it * 128;
            const int row = u >> 3, c16 = u & 7;
            const uint32_t so = SWZ((uint32_t)(row * 128 + c16 * 16));
            const ll g = (ll)(n0 + row) * ldb + kc + c16 * 8;
            cpa16(bo + 2 * TA + so, Bh + g);
            cpa16(bo + 2 * TA + TBb + so, Bl + g);
        }
        cpa_commit();
    };

    const int wid = tid >> 5, lane = tid & 31;
    const int m0w = wid * 32;
    const int lrow = lane & 15, lcol = lane >> 4;

    float acc[2][8][4];
#pragma unroll
    for (int i = 0; i < 2; i++)
#pragma unroll
        for (int j = 0; j < 8; j++)
#pragma unroll
            for (int q = 0; q < 4; q++) acc[i][j][q] = 0.f;

    const int nC = K >> 6;
    load_chunk(0);

    for (int c = 0; c < nC; ++c) {
        if (c + 1 < nC) { load_chunk(c + 1); cpa_wait<1>(); }
        else           { cpa_wait<0>(); }
        __syncthreads();

        const int buf = c & 1;
        const uint32_t As_h = sb + buf * STRIDE;
        const uint32_t As_l = As_h + TA;
        const uint32_t Bs_h = As_h + 2 * TA;
        const uint32_t Bs_l = Bs_h + TBb;

#pragma unroll
        for (int k16 = 0; k16 < 4; ++k16) {
            const uint32_t kb = k16 * 32;
            uint32_t ah[2][4], al[2][4];
#pragma unroll
            for (int i = 0; i < 2; ++i) {
                const uint32_t off = SWZ((uint32_t)((m0w + i * 16 + lrow) * 128) + kb + lcol * 16);
                ldmx4(ah[i], As_h + off);
                ldmx4(al[i], As_l + off);
            }
            uint32_t bh[8][2], bl[8][2];
#pragma unroll
            for (int p = 0; p < 4; ++p) {
                const uint32_t off = SWZ((uint32_t)((p * 16 + lrow) * 128) + kb + lcol * 16);
                uint32_t r[4];
                ldmx4(r, Bs_h + off);
                bh[2 * p][0] = r[0]; bh[2 * p][1] = r[2];
                bh[2 * p + 1][0] = r[1]; bh[2 * p + 1][1] = r[3];
                ldmx4(r, Bs_l + off);
                bl[2 * p][0] = r[0]; bl[2 * p][1] = r[2];
                bl[2 * p + 1][0] = r[1]; bl[2 * p + 1][1] = r[3];
            }
#pragma unroll
            for (int i = 0; i < 2; ++i)
#pragma unroll
                for (int j = 0; j < 8; ++j) {
                    mma16816(acc[i][j], ah[i], bh[j]);
                    mma16816(acc[i][j], ah[i], bl[j]);
                    mma16816(acc[i][j], al[i], bh[j]);
                }
        }
        __syncthreads();
    }

    const int gID = lane >> 2;
    const int tc2 = (lane & 3) * 2;

    if (OUTT) {
        constexpr int PADC = 66;
        __half* SH = (__half*)dsm;
        __half* SL = SH + 128 * PADC;
#pragma unroll
        for (int i = 0; i < 2; ++i) {
            const int r0l = m0w + i * 16 + gID;
#pragma unroll
            for (int j = 0; j < 8; ++j) {
                const int cl = j * 8 + tc2;
                float c0 = acc[i][j][0] * alpha, c1 = acc[i][j][1] * alpha;
                float c2 = acc[i][j][2] * alpha, c3 = acc[i][j][3] * alpha;
                if (bias) {
                    const float b0 = bias[n0 + cl], b1 = bias[n0 + cl + 1];
                    c0 += b0; c1 += b1; c2 += b0; c3 += b1;
                }
                __half h, l;
                split2(c0, h, l); SH[r0l * PADC + cl] = h;       SL[r0l * PADC + cl] = l;
                split2(c1, h, l); SH[r0l * PADC + cl + 1] = h;   SL[r0l * PADC + cl + 1] = l;
                split2(c2, h, l); SH[(r0l + 8) * PADC + cl] = h; SL[(r0l + 8) * PADC + cl] = l;
                split2(c3, h, l); SH[(r0l + 8) * PADC + cl + 1] = h; SL[(r0l + 8) * PADC + cl + 1] = l;
            }
        }
        __syncthreads();
        const int bT = m0 >> 12;
        const int t0 = m0 & 4095;
        const int ch = tid & 63;
        const int hf = tid >> 6;
        const ll dbase = (ll)bT * 1024 * 4096 + (ll)(n0 + ch) * 4096 + t0 + hf * 64;
#pragma unroll
        for (int s8 = 0; s8 < 8; ++s8) {
            __half th[8], tl[8];
#pragma unroll
            for (int e = 0; e < 8; ++e) {
                const int tok = hf * 64 + s8 * 8 + e;
                th[e] = SH[tok * PADC + ch];
                tl[e] = SL[tok * PADC + ch];
            }
            *(uint4*)(Chz + dbase + s8 * 8) = *(uint4*)th;
            *(uint4*)(Clz + dbase + s8 * 8) = *(uint4*)tl;
        }
        return;
    }

#pragma unroll
    for (int i = 0; i < 2; ++i) {
        const int rA = m0 + m0w + i * 16 + gID;
        const int rB = rA + 8;
#pragma unroll
        for (int j = 0; j < 8; ++j) {
            const int col = n0 + j * 8 + tc2;
            float c0 = acc[i][j][0] * alpha, c1 = acc[i][j][1] * alpha;
            float c2 = acc[i][j][2] * alpha, c3 = acc[i][j][3] * alpha;
            if (bias) {
                const float b0 = bias[col], b1 = bias[col + 1];
                c0 += b0; c1 += b1; c2 += b0; c3 += b1;
            }
            if (OUTF) {
                *(float2*)(Cfz + (ll)rA * ldc + col) = make_float2(c0, c1);
                *(float2*)(Cfz + (ll)rB * ldc + col) = make_float2(c2, c3);
            }
            if (OUTS) {
                __half h0, l0, h1, l1;
                split2(c0, h0, l0); split2(c1, h1, l1);
                *(uint32_t*)(Chz + (ll)rA * ldc + col) = pack_h2(h0, h1);
                *(uint32_t*)(Clz + (ll)rA * ldc + col) = pack_h2(l0, l1);
                split2(c2, h0, l0); split2(c3, h1, l1);
                *(uint32_t*)(Chz + (ll)rB * ldc + col) = pack_h2(h0, h1);
                *(uint32_t*)(Clz + (ll)rB * ldc + col) = pack_h2(l0, l1);
            }
        }
    }
}

// ============================ fused softmax+AV kernel ============================
__global__ __launch_bounds__(128, 2) void av_fused(
    const float* __restrict__ scores, const float2* __restrict__ stats,
    const __half* __restrict__ VpTh, const __half* __restrict__ VpTl,
    __half* __restrict__ Ch, __half* __restrict__ Cl)
{
    extern __shared__ char dsm[];
    constexpr int TAH = 128 * 128;
    constexpr int TBH = 64 * 128;

    const int z = blockIdx.z;
    const int b = z >> 4, h = z & 15;
    const int t0g = blockIdx.y * 128;
    const int tid = threadIdx.x;
    const uint32_t sb = smem_u32(dsm);
    const uint32_t aH = sb, aL = sb + TAH;
    const uint32_t bBase = sb + 2 * TAH;

    const float* sc = scores + ((ll)z * 4096 + t0g) * 256;
    const float2 st = stats[(ll)z * 4096 + t0g + tid];
    const float mx = st.x, inv = st.y;
    const __half* Bh = VpTh + (ll)b * 1024 * 256 + (ll)h * 64 * 256;
    const __half* Bl = VpTl + (ll)b * 1024 * 256 + (ll)h * 64 * 256;
    __half* Chz = Ch + (ll)b * 4096 * 1024 + (ll)t0g * 1024 + h * 64;
    __half* Clz = Cl + (ll)b * 4096 * 1024 + (ll)t0g * 1024 + h * 64;

    auto load_B = [&](int c) {
        const uint32_t bo = bBase + (c & 1) * 2 * TBH;
        const ll kc = (ll)c * 64;
#pragma unroll
        for (int it = 0; it < 4; ++it) {
            const int u = tid + it * 128;
            const int row = u >> 3, c16 = u & 7;
            const uint32_t so = SWZ((uint32_t)(row * 128 + c16 * 16));
            const ll g = (ll)row * 256 + kc + c16 * 8;
            cpa16(bo + so, Bh + g);
            cpa16(bo + TBH + so, Bl + g);
        }
        cpa_commit();
    };

    auto convert_sts = [&](const float4* ar) {
#pragma unroll
        for (int j = 0; j < 8; ++j) {
            float v[8];
            const float4 p0 = ar[2 * j], p1 = ar[2 * j + 1];
            v[0] = p0.x; v[1] = p0.y; v[2] = p0.z; v[3] = p0.w;
            v[4] = p1.x; v[5] = p1.y; v[6] = p1.z; v[7] = p1.w;
            __half hh[8], llw[8];
#pragma unroll
            for (int e = 0; e < 8; ++e) {
                const float a = __expf(v[e] - mx) * inv;
                split2(a, hh[e], llw[e]);
            }
            const uint32_t so = SWZ((uint32_t)(tid * 128 + j * 16));
            *(uint4*)(dsm + (aH - sb) + so) = *(const uint4*)hh;
            *(uint4*)(dsm + (aL - sb) + so) = *(const uint4*)llw;
        }
    };

    const int wid = tid >> 5, lane = tid & 31;
    const int m0w = wid * 32;
    const int lrow = lane & 15, lcol = lane >> 4;

    float acc[2][8][4];
#pragma unroll
    for (int i = 0; i < 2; i++)
#pragma unroll
        for (int j = 0; j < 8; j++)
#pragma unroll
            for (int q = 0; q < 4; q++) acc[i][j][q] = 0.f;

    load_B(0);
    float4 ar[16], ar2[16];
    const float4* scf = (const float4*)(sc + (ll)tid * 256);
#pragma unroll
    for (int i = 0; i < 16; ++i) ar[i] = scf[i];

    for (int c = 0; c < 4; ++c) {
        if (c < 3) load_B(c + 1);
        convert_sts(ar);
        if (c < 3) {
#pragma unroll
            for (int i = 0; i < 16; ++i) ar2[i] = scf[(c + 1) * 16 + i];
        }
        if (c < 3) cpa_wait<1>(); else cpa_wait<0>();
        __syncthreads();

        const uint32_t Bs_h = bBase + (c & 1) * 2 * TBH;
        const uint32_t Bs_l = Bs_h + TBH;
#pragma unroll
        for (int k16 = 0; k16 < 4; ++k16) {
            const uint32_t kb = k16 * 32;
            uint32_t ah[2][4], al[2][4];
#pragma unroll
            for (int i = 0; i < 2; ++i) {
                const uint32_t off = SWZ((uint32_t)((m0w + i * 16 + lrow) * 128) + kb + lcol * 16);
                ldmx4(ah[i], aH + off);
                ldmx4(al[i], aL + off);
            }
            uint32_t bh[8][2], bl[8][2];
#pragma unroll
            for (int p = 0; p < 4; ++p) {
                const uint32_t off = SWZ((uint32_t)((p * 16 + lrow) * 128) + kb + lcol * 16);
                uint32_t r[4];
                ldmx4(r, Bs_h + off);
                bh[2 * p][0] = r[0]; bh[2 * p][1] = r[2];
                bh[2 * p + 1][0] = r[1]; bh[2 * p + 1][1] = r[3];
                ldmx4(r, Bs_l + off);
                bl[2 * p][0] = r[0]; bl[2 * p][1] = r[2];
                bl[2 * p + 1][0] = r[1]; bl[2 * p + 1][1] = r[3];
            }
#pragma unroll
            for (int i = 0; i < 2; ++i)
#pragma unroll
                for (int j = 0; j < 8; ++j) {
                    mma16816(acc[i][j], ah[i], bh[j]);
                    mma16816(acc[i][j], ah[i], bl[j]);
                    mma16816(acc[i][j], al[i], bh[j]);
                }
        }
        __syncthreads();
#pragma unroll
        for (int i = 0; i < 16; ++i) ar[i] = ar2[i];
    }

    const int gID = lane >> 2;
    const int tc2 = (lane & 3) * 2;
#pragma unroll
    for (int i = 0; i < 2; ++i) {
        const int rA = m0w + i * 16 + gID;
        const int rB = rA + 8;
#pragma unroll
        for (int j = 0; j < 8; ++j) {
            const int col = j * 8 + tc2;
            const float c0 = acc[i][j][0], c1 = acc[i][j][1];
            const float c2 = acc[i][j][2], c3 = acc[i][j][3];
            __half h0, l0, h1, l1;
            split2(c0, h0, l0); split2(c1, h1, l1);
            *(uint32_t*)(Chz + (ll)rA * 1024 + col) = pack_h2(h0, h1);
            *(uint32_t*)(Clz + (ll)rA * 1024 + col) = pack_h2(l0, l1);
            split2(c2, h0, l0); split2(c3, h1, l1);
            *(uint32_t*)(Chz + (ll)rB * 1024 + col) = pack_h2(h0, h1);
            *(uint32_t*)(Clz + (ll)rB * 1024 + col) = pack_h2(l0, l1);
        }
    }
}

// ============================ host launch ============================
extern "C" void kernel_launch(void* const* d_in, const int* in_sizes, int n_in,
                              void* d_out, int out_size)
{
    const float* x  = (const float*)d_in[0];
    const float* Wq = (const float*)d_in[1];
    const float* bq = (const float*)d_in[2];
    const float* Wk = (const float*)d_in[3];
    const float* bk = (const float*)d_in[4];
    const float* Wv = (const float*)d_in[5];
    const float* bv = (const float*)d_in[6];
    const float* E  = (const float*)d_in[7];
    const float* F  = (const float*)d_in[8];
    const float* Wo = (const float*)d_in[9];
    const float* bo = (const float*)d_in[10];

    float* out    = (float*)d_out;                 // (4,4096,1024)
    float* scores = out + (ll)4 * 4096 * 1024;     // (4,16,4096,256)

    __half* P;
    cudaGetSymbolAddress((void**)&P, g_pool4);
#define PP(o) (P + (o))

    auto G1  = gemm_mma<false, true,  false>;  // split fp16 out
    auto G1T = gemm_mma<false, false, true>;   // split fp16 out, transposed
    auto G2  = gemm_mma<true,  false, false>;  // fp32 out
    const int DYN = 2 * (2 * 128 * 128 + 2 * 64 * 128);  // 98304
    const int DYNAV = 2 * 128 * 128 + 2 * 2 * 64 * 128;  // 65536
    cudaFuncSetAttribute(G1,  cudaFuncAttributeMaxDynamicSharedMemorySize, DYN);
    cudaFuncSetAttribute(G1T, cudaFuncAttributeMaxDynamicSharedMemorySize, DYN);
    cudaFuncSetAttribute(G2,  cudaFuncAttributeMaxDynamicSharedMemorySize, DYN);
    cudaFuncSetAttribute(av_fused, cudaFuncAttributeMaxDynamicSharedMemorySize, DYNAV);

    float* pk = (float*)PP(o_pk);   // Kp partials: [2][4*256*1024]
    float* pv = (float*)PP(o_pv);   // Vp partials: [2][4*1024*256]

    // 1) converts (2 launches)
    convert_split<<<(int)(NX / 4 / 256), 256>>>(x, PP(o_xh), PP(o_xl), (int)(NX / 4));
    {
        P6 p;
        p.s[0] = Wq; p.h[0] = PP(o_wqh); p.l[0] = PP(o_wql);
        p.s[1] = Wk; p.h[1] = PP(o_wkh); p.l[1] = PP(o_wkl);
        p.s[2] = Wv; p.h[2] = PP(o_wvh); p.l[2] = PP(o_wvl);
        p.s[3] = Wo; p.h[3] = PP(o_woh); p.l[3] = PP(o_wol);
        p.s[4] = E;  p.h[4] = PP(o_eh);  p.l[4] = PP(o_el);
        p.s[5] = F;  p.h[5] = PP(o_fh);  p.l[5] = PP(o_fl);
        convert6<<<dim3((int)(NW / 4 / 256), 1, 6), 256>>>(p, (int)(NW / 4));
    }

    // 2) projections: Q normal; K,V write transposed split directly
    {
        dim3 g(16, 128, 1);
        G1<<<g, 128, DYN>>>(PP(o_xh), PP(o_xl), PP(o_wqh), PP(o_wql), bq,
                            nullptr, PP(o_qh), PP(o_ql),
                            1024, 1024, 1024, 1024, 0, 0, 0, 0, 0, 0, 1, 1.0f);
        G1T<<<g, 128, DYN>>>(PP(o_xh), PP(o_xl), PP(o_wkh), PP(o_wkl), bk,
                             nullptr, PP(o_kth), PP(o_ktl),
                             1024, 1024, 1024, 0, 0, 0, 0, 0, 0, 0, 1, 1.0f);
        G1T<<<g, 128, DYN>>>(PP(o_xh), PP(o_xl), PP(o_wvh), PP(o_wvl), bv,
                             nullptr, PP(o_vth), PP(o_vtl),
                             1024, 1024, 1024, 0, 0, 0, 0, 0, 0, 0, 1, 1.0f);
    }

    // 3) Kp split-K=2: partial[s][b](256x1024) = E[:, s*2048:] * Kt[b][:, s*2048:]^T
    //    grid z = b*2 + s (zInner=2)
    G2<<<dim3(16, 2, 8), 128, DYN>>>(PP(o_eh), PP(o_el), PP(o_kth), PP(o_ktl), nullptr,
                                     pk, nullptr, nullptr,
                                     2048, 4096, 4096, 1024,
                                     0, 2048,                    // A: E (batch-shared), split offset
                                     (ll)1024 * 4096, 2048,      // B: Kt batch stride, split offset
                                     (ll)256 * 1024, (ll)4 * 256 * 1024,  // C: batch, split-buffer
                                     2, 1.0f);
    // 4) Vp split-K=2: partial[s][b](1024x256) = Vt[b][:, s*2048:] * F[:, s*2048:]^T
    G2<<<dim3(4, 8, 8), 128, DYN>>>(PP(o_vth), PP(o_vtl), PP(o_fh), PP(o_fl), nullptr,
                                    pv, nullptr, nullptr,
                                    2048, 4096, 4096, 256,
                                    (ll)1024 * 4096, 2048,       // A: Vt batch stride, split offset
                                    0, 2048,                     // B: F (batch-shared), split offset
                                    (ll)1024 * 256, (ll)4 * 1024 * 256,
                                    2, 1.0f);
    // combine partials -> split fp16
    add_split<<<(4 * 256 * 1024 / 4 + 255) / 256, 256>>>(pk, pk + (ll)4 * 256 * 1024,
                                                         PP(o_kph), PP(o_kpl), 4 * 256 * 1024 / 4);
    add_split<<<(4 * 1024 * 256 / 4 + 255) / 256, 256>>>(pv, pv + (ll)4 * 1024 * 256,
                                                         PP(o_vph), PP(o_vpl), 4 * 1024 * 256 / 4);

    // 5) scores[b,h](4096x256) = Q_h(4096x64) * Kp_h^T / 8  -> fp32 into d_out
    G2<<<dim3(4, 32, 64), 128, DYN>>>(PP(o_qh), PP(o_ql), PP(o_kph), PP(o_kpl), nullptr,
                                      scores, nullptr, nullptr,
                                      64, 1024, 1024, 256,
                                      (ll)4096 * 1024, 64, (ll)256 * 1024, 64,
                                      (ll)16 * 4096 * 256, (ll)4096 * 256, 16, 0.125f);

    // 6) softmax stats
    softmax_stats<<<(4 * 16 * 4096) / 4, 128>>>(scores, (float2*)PP(o_st));

    // 7) fused softmax+AV
    av_fused<<<dim3(1, 32, 64), 128, DYNAV>>>(scores, (const float2*)PP(o_st),
                                              PP(o_vph), PP(o_vpl),
                                              PP(o_ohh), PP(o_ohl));

    // 8) out = outh * Wo^T + bo
    G2<<<dim3(16, 128, 1), 128, DYN>>>(PP(o_ohh), PP(o_ohl), PP(o_woh), PP(o_wol), bo,
                                       out, nullptr, nullptr,
                                       1024, 1024, 1024, 1024,
                                       0, 0, 0, 0, 0, 0, 1, 1.0f);
#undef PP
}

// round 16
// speedup vs baseline: 1.1819x; 1.1690x over previous
#include <cuda_runtime.h>
#include <cuda_fp16.h>
#include <cstdint>

typedef long long ll;

// ============================ helpers ============================
__device__ __forceinline__ uint32_t smem_u32(const void* p) {
    uint32_t a;
    asm("{ .reg .u64 t; cvta.to.shared.u64 t, %1; cvt.u32.u64 %0, t; }" : "=r"(a) : "l"(p));
    return a;
}
#define SWZ(o) ((o) ^ (((o) >> 3) & 0x70))

__device__ __forceinline__ void cpa16(uint32_t dst, const void* src) {
    asm volatile("cp.async.cg.shared.global [%0], [%1], 16;" :: "r"(dst), "l"(src));
}
__device__ __forceinline__ void cpa_commit() {
    asm volatile("cp.async.commit_group;");
}
template <int N>
__device__ __forceinline__ void cpa_wait() {
    asm volatile("cp.async.wait_group %0;" :: "n"(N));
}
__device__ __forceinline__ void ldmx4(uint32_t* r, uint32_t addr) {
    asm volatile("ldmatrix.sync.aligned.m8n8.x4.shared.b16 {%0,%1,%2,%3}, [%4];"
                 : "=r"(r[0]), "=r"(r[1]), "=r"(r[2]), "=r"(r[3]) : "r"(addr));
}
__device__ __forceinline__ void mma16816(float* c, const uint32_t* a, const uint32_t* b) {
    asm volatile(
        "mma.sync.aligned.m16n8k16.row.col.f32.f16.f16.f32 "
        "{%0,%1,%2,%3}, {%4,%5,%6,%7}, {%8,%9}, {%0,%1,%2,%3};"
        : "+f"(c[0]), "+f"(c[1]), "+f"(c[2]), "+f"(c[3])
        : "r"(a[0]), "r"(a[1]), "r"(a[2]), "r"(a[3]), "r"(b[0]), "r"(b[1]));
}
__device__ __forceinline__ void split2(float v, __half& h, __half& l) {
    h = __float2half_rn(v);
    l = __float2half_rn(v - __half2float(h));
}
__device__ __forceinline__ uint32_t pack_h2(__half a, __half b) {
    __half2 t = __halves2half2(a, b);
    return *(uint32_t*)&t;
}

// ============================ scratch pool ============================
static constexpr size_t NX   = (size_t)4 * 4096 * 1024;
static constexpr size_t NW   = (size_t)1024 * 1024;
static constexpr size_t NATT = (size_t)4 * 16 * 4096 * 256;

static constexpr size_t o_xh  = 0;
static constexpr size_t o_xl  = o_xh  + NX;
static constexpr size_t o_qh  = o_xl  + NX;
static constexpr size_t o_ql  = o_qh  + NX;
static constexpr size_t o_kth = o_ql  + NX;
static constexpr size_t o_ktl = o_kth + NX;
static constexpr size_t o_vth = o_ktl + NX;
static constexpr size_t o_vtl = o_vth + NX;
static constexpr size_t o_ohh = o_vtl + NX;
static constexpr size_t o_ohl = o_ohh + NX;   // unused now (kept for layout stability)
static constexpr size_t o_wqh = o_ohl + NX;
static constexpr size_t o_wql = o_wqh + NW;
static constexpr size_t o_wkh = o_wql + NW;
static constexpr size_t o_wkl = o_wkh + NW;
static constexpr size_t o_wvh = o_wkl + NW;
static constexpr size_t o_wvl = o_wvh + NW;
static constexpr size_t o_woh = o_wvl + NW;
static constexpr size_t o_wol = o_woh + NW;
static constexpr size_t o_eh  = o_wol + NW;
static constexpr size_t o_el  = o_eh  + NW;
static constexpr size_t o_fh  = o_el  + NW;
static constexpr size_t o_fl  = o_fh  + NW;
static constexpr size_t o_kph = o_fl  + NW;
static constexpr size_t o_kpl = o_kph + NW;
static constexpr size_t o_vph = o_kpl + NW;
static constexpr size_t o_vpl = o_vph + NW;
static constexpr size_t o_st  = o_vpl + NW;        // stats float2
static constexpr size_t o_pk  = o_st + 4194304;    // Kp fp32 partials (2 x 1M floats)
static constexpr size_t o_pv  = o_pk + 4194304;    // Vp fp32 partials
static constexpr size_t POOL_ELTS = o_st + NATT;

__device__ uint4 g_pool4[(POOL_ELTS * 2 + 15) / 16];

// ============================ convert: fp32 -> split fp16 ============================
__global__ __launch_bounds__(256) void convert_split(
    const float* __restrict__ src, __half* __restrict__ H,
    __half* __restrict__ L, int n4)
{
    int i = blockIdx.x * 256 + threadIdx.x;
    if (i >= n4) return;
    float4 v = ((const float4*)src)[i];
    __half h0, l0, h1, l1, h2, l2, h3, l3;
    split2(v.x, h0, l0); split2(v.y, h1, l1);
    split2(v.z, h2, l2); split2(v.w, h3, l3);
    ((uint2*)H)[i] = make_uint2(pack_h2(h0, h1), pack_h2(h2, h3));
    ((uint2*)L)[i] = make_uint2(pack_h2(l0, l1), pack_h2(l2, l3));
}

// add two fp32 partials, emit split fp16
__global__ __launch_bounds__(256) void add_split(
    const float* __restrict__ P0, const float* __restrict__ P1,
    __half* __restrict__ H, __half* __restrict__ L, int n4)
{
    int i = blockIdx.x * 256 + threadIdx.x;
    if (i >= n4) return;
    float4 a = ((const float4*)P0)[i];
    float4 b = ((const float4*)P1)[i];
    a.x += b.x; a.y += b.y; a.z += b.z; a.w += b.w;
    __half h0, l0, h1, l1, h2, l2, h3, l3;
    split2(a.x, h0, l0); split2(a.y, h1, l1);
    split2(a.z, h2, l2); split2(a.w, h3, l3);
    ((uint2*)H)[i] = make_uint2(pack_h2(h0, h1), pack_h2(h2, h3));
    ((uint2*)L)[i] = make_uint2(pack_h2(l0, l1), pack_h2(l2, l3));
}

struct P6 { const float* s[6]; __half* h[6]; __half* l[6]; };
__global__ __launch_bounds__(256) void convert6(P6 p, int n4)
{
    const int z = blockIdx.z;
    const float* src = p.s[z];
    __half* H = p.h[z];
    __half* L = p.l[z];
    int i = blockIdx.x * 256 + threadIdx.x;
    if (i >= n4) return;
    float4 v = ((const float4*)src)[i];
    __half h0, l0, h1, l1, h2, l2, h3, l3;
    split2(v.x, h0, l0); split2(v.y, h1, l1);
    split2(v.z, h2, l2); split2(v.w, h3, l3);
    ((uint2*)H)[i] = make_uint2(pack_h2(h0, h1), pack_h2(h2, h3));
    ((uint2*)L)[i] = make_uint2(pack_h2(l0, l1), pack_h2(l2, l3));
}

// ============================ softmax stats: per-row max & 1/sum ============================
__global__ __launch_bounds__(128) void softmax_stats(
    const float* __restrict__ s, float2* __restrict__ st)
{
    const int row = blockIdx.x * 4 + (threadIdx.x >> 5);
    const int lane = threadIdx.x & 31;
    const float* sp = s + (ll)row * 256 + lane * 8;
    float4 a = *(const float4*)sp;
    float4 b = *(const float4*)(sp + 4);
    float v[8] = {a.x, a.y, a.z, a.w, b.x, b.y, b.z, b.w};
    float mx = -3.4e38f;
#pragma unroll
    for (int i = 0; i < 8; i++) mx = fmaxf(mx, v[i]);
#pragma unroll
    for (int o = 16; o > 0; o >>= 1) mx = fmaxf(mx, __shfl_xor_sync(0xffffffffu, mx, o));
    float sum = 0.f;
#pragma unroll
    for (int i = 0; i < 8; i++) { v[i] = __expf(v[i] - mx); sum += v[i]; }
#pragma unroll
    for (int o = 16; o > 0; o >>= 1) sum += __shfl_xor_sync(0xffffffffu, sum, o);
    if (lane == 0) st[row] = make_float2(mx, 1.0f / sum);
}

// ============================ split-fp16 GEMM: 128 thr, tile 128x64x64, 2 CTAs/SM ============================
// TERMS=3: C = (Ah+Al)(Bh+Bl) minus al*bl.  TERMS=2: C = Ah*(Bh+Bl)  (A rounded to fp16).
template <bool OUTF, bool OUTS, bool OUTT, int TERMS>
__global__ __launch_bounds__(128, 2) void gemm_mma(
    const __half* __restrict__ Ah, const __half* __restrict__ Al,
    const __half* __restrict__ Bh, const __half* __restrict__ Bl,
    const float* __restrict__ bias,
    float* __restrict__ Cf, __half* __restrict__ Ch, __half* __restrict__ Cl,
    int K, int lda, int ldb, int ldc,
    ll sAo, ll sAi, ll sBo, ll sBi, ll sCo, ll sCi, int zInner, float alpha)
{
    extern __shared__ char dsm[];
    constexpr int TA = 128 * 128;
    constexpr int TBb = 64 * 128;
    constexpr int STRIDE = 2 * TA + 2 * TBb;

    const int zo = blockIdx.z / zInner, zi = blockIdx.z - zo * zInner;
    Ah += zo * sAo + zi * sAi;  Al += zo * sAo + zi * sAi;
    Bh += zo * sBo + zi * sBi;  Bl += zo * sBo + zi * sBi;
    float* Cfz = OUTF ? (Cf + zo * sCo + zi * sCi) : nullptr;
    __half* Chz = (OUTS || OUTT) ? (Ch + (OUTT ? 0 : zo * sCo + zi * sCi)) : nullptr;
    __half* Clz = (OUTS || OUTT) ? (Cl + (OUTT ? 0 : zo * sCo + zi * sCi)) : nullptr;

    const int m0 = blockIdx.y * 128;
    const int n0 = blockIdx.x * 64;
    const int tid = threadIdx.x;
    const uint32_t sb = smem_u32(dsm);

    auto load_chunk = [&](int c) {
        const int buf = c & 1;
        const uint32_t bo = sb + buf * STRIDE;
        const ll kc = (ll)c * 64;
#pragma unroll
        for (int it = 0; it < 8; ++it) {
            const int u = tid + it * 128;
            const int row = u >> 3, c16 = u & 7;
            const uint32_t so = SWZ((uint32_t)(row * 128 + c16 * 16));
            const ll g = (ll)(m0 + row) * lda + kc + c16 * 8;
            cpa16(bo + so, Ah + g);
            if (TERMS == 3) cpa16(bo + TA + so, Al + g);
        }
#pragma unroll
        for (int it = 0; it < 4; ++it) {
            const int u = tid + it * 128;
            const int row = u >> 3, c16 = u & 7;
            const uint32_t so = SWZ((uint32_t)(row * 128 + c16 * 16));
            const ll g = (ll)(n0 + row) * ldb + kc + c16 * 8;
            cpa16(bo + 2 * TA + so, Bh + g);
            cpa16(bo + 2 * TA + TBb + so, Bl + g);
        }
        cpa_commit();
    };

    const int wid = tid >> 5, lane = tid & 31;
    const int m0w = wid * 32;
    const int lrow = lane & 15, lcol = lane >> 4;

    float acc[2][8][4];
#pragma unroll
    for (int i = 0; i < 2; i++)
#pragma unroll
        for (int j = 0; j < 8; j++)
#pragma unroll
            for (int q = 0; q < 4; q++) acc[i][j][q] = 0.f;

    const int nC = K >> 6;
    load_chunk(0);

    for (int c = 0; c < nC; ++c) {
        if (c + 1 < nC) { load_chunk(c + 1); cpa_wait<1>(); }
        else           { cpa_wait<0>(); }
        __syncthreads();

        const int buf = c & 1;
        const uint32_t As_h = sb + buf * STRIDE;
        const uint32_t As_l = As_h + TA;
        const uint32_t Bs_h = As_h + 2 * TA;
        const uint32_t Bs_l = Bs_h + TBb;

#pragma unroll
        for (int k16 = 0; k16 < 4; ++k16) {
            const uint32_t kb = k16 * 32;
            uint32_t ah[2][4], al[2][4];
#pragma unroll
            for (int i = 0; i < 2; ++i) {
                const uint32_t off = SWZ((uint32_t)((m0w + i * 16 + lrow) * 128) + kb + lcol * 16);
                ldmx4(ah[i], As_h + off);
                if (TERMS == 3) ldmx4(al[i], As_l + off);
            }
            uint32_t bh[8][2], bl[8][2];
#pragma unroll
            for (int p = 0; p < 4; ++p) {
                const uint32_t off = SWZ((uint32_t)((p * 16 + lrow) * 128) + kb + lcol * 16);
                uint32_t r[4];
                ldmx4(r, Bs_h + off);
                bh[2 * p][0] = r[0]; bh[2 * p][1] = r[2];
                bh[2 * p + 1][0] = r[1]; bh[2 * p + 1][1] = r[3];
                ldmx4(r, Bs_l + off);
                bl[2 * p][0] = r[0]; bl[2 * p][1] = r[2];
                bl[2 * p + 1][0] = r[1]; bl[2 * p + 1][1] = r[3];
            }
#pragma unroll
            for (int i = 0; i < 2; ++i)
#pragma unroll
                for (int j = 0; j < 8; ++j) {
                    mma16816(acc[i][j], ah[i], bh[j]);
                    mma16816(acc[i][j], ah[i], bl[j]);
                    if (TERMS == 3) mma16816(acc[i][j], al[i], bh[j]);
                }
        }
        __syncthreads();
    }

    const int gID = lane >> 2;
    const int tc2 = (lane & 3) * 2;

    if (OUTT) {
        constexpr int PADC = 66;
        __half* SH = (__half*)dsm;
        __half* SL = SH + 128 * PADC;
#pragma unroll
        for (int i = 0; i < 2; ++i) {
            const int r0l = m0w + i * 16 + gID;
#pragma unroll
            for (int j = 0; j < 8; ++j) {
                const int cl = j * 8 + tc2;
                float c0 = acc[i][j][0] * alpha, c1 = acc[i][j][1] * alpha;
                float c2 = acc[i][j][2] * alpha, c3 = acc[i][j][3] * alpha;
                if (bias) {
                    const float b0 = bias[n0 + cl], b1 = bias[n0 + cl + 1];
                    c0 += b0; c1 += b1; c2 += b0; c3 += b1;
                }
                __half h, l;
                split2(c0, h, l); SH[r0l * PADC + cl] = h;       SL[r0l * PADC + cl] = l;
                split2(c1, h, l); SH[r0l * PADC + cl + 1] = h;   SL[r0l * PADC + cl + 1] = l;
                split2(c2, h, l); SH[(r0l + 8) * PADC + cl] = h; SL[(r0l + 8) * PADC + cl] = l;
                split2(c3, h, l); SH[(r0l + 8) * PADC + cl + 1] = h; SL[(r0l + 8) * PADC + cl + 1] = l;
            }
        }
        __syncthreads();
        const int bT = m0 >> 12;
        const int t0 = m0 & 4095;
        const int ch = tid & 63;
        const int hf = tid >> 6;
        const ll dbase = (ll)bT * 1024 * 4096 + (ll)(n0 + ch) * 4096 + t0 + hf * 64;
#pragma unroll
        for (int s8 = 0; s8 < 8; ++s8) {
            __half th[8], tl[8];
#pragma unroll
            for (int e = 0; e < 8; ++e) {
                const int tok = hf * 64 + s8 * 8 + e;
                th[e] = SH[tok * PADC + ch];
                tl[e] = SL[tok * PADC + ch];
            }
            *(uint4*)(Chz + dbase + s8 * 8) = *(uint4*)th;
            *(uint4*)(Clz + dbase + s8 * 8) = *(uint4*)tl;
        }
        return;
    }

#pragma unroll
    for (int i = 0; i < 2; ++i) {
        const int rA = m0 + m0w + i * 16 + gID;
        const int rB = rA + 8;
#pragma unroll
        for (int j = 0; j < 8; ++j) {
            const int col = n0 + j * 8 + tc2;
            float c0 = acc[i][j][0] * alpha, c1 = acc[i][j][1] * alpha;
            float c2 = acc[i][j][2] * alpha, c3 = acc[i][j][3] * alpha;
            if (bias) {
                const float b0 = bias[col], b1 = bias[col + 1];
                c0 += b0; c1 += b1; c2 += b0; c3 += b1;
            }
            if (OUTF) {
                *(float2*)(Cfz + (ll)rA * ldc + col) = make_float2(c0, c1);
                *(float2*)(Cfz + (ll)rB * ldc + col) = make_float2(c2, c3);
            }
            if (OUTS) {
                __half h0, l0, h1, l1;
                split2(c0, h0, l0); split2(c1, h1, l1);
                *(uint32_t*)(Chz + (ll)rA * ldc + col) = pack_h2(h0, h1);
                *(uint32_t*)(Clz + (ll)rA * ldc + col) = pack_h2(l0, l1);
                split2(c2, h0, l0); split2(c3, h1, l1);
                *(uint32_t*)(Chz + (ll)rB * ldc + col) = pack_h2(h0, h1);
                *(uint32_t*)(Clz + (ll)rB * ldc + col) = pack_h2(l0, l1);
            }
        }
    }
}

// ============================ fused softmax+AV kernel (2-term: attn rounded to fp16) ============================
// A = fp16(softmax(scores)) tile 128x256; B = VpT hi+lo; C = outh hi only (fp16), ldc=1024.
__global__ __launch_bounds__(128, 2) void av_fused(
    const float* __restrict__ scores, const float2* __restrict__ stats,
    const __half* __restrict__ VpTh, const __half* __restrict__ VpTl,
    __half* __restrict__ Ch)
{
    extern __shared__ char dsm[];
    constexpr int TAH = 128 * 128;     // A hi: 16 KB
    constexpr int TBH = 64 * 128;      // B part: 8 KB
    // layout: [A hi 16K][B s0 hi|lo 16K][B s1 hi|lo 16K] = 48 KB

    const int z = blockIdx.z;
    const int b = z >> 4, h = z & 15;
    const int t0g = blockIdx.y * 128;
    const int tid = threadIdx.x;
    const uint32_t sb = smem_u32(dsm);
    const uint32_t aH = sb;
    const uint32_t bBase = sb + TAH;

    const float* sc = scores + ((ll)z * 4096 + t0g) * 256;
    const float2 st = stats[(ll)z * 4096 + t0g + tid];
    const float mx = st.x, inv = st.y;
    const __half* Bh = VpTh + (ll)b * 1024 * 256 + (ll)h * 64 * 256;
    const __half* Bl = VpTl + (ll)b * 1024 * 256 + (ll)h * 64 * 256;
    __half* Chz = Ch + (ll)b * 4096 * 1024 + (ll)t0g * 1024 + h * 64;

    auto load_B = [&](int c) {
        const uint32_t bo = bBase + (c & 1) * 2 * TBH;
        const ll kc = (ll)c * 64;
#pragma unroll
        for (int it = 0; it < 4; ++it) {
            const int u = tid + it * 128;
            const int row = u >> 3, c16 = u & 7;
            const uint32_t so = SWZ((uint32_t)(row * 128 + c16 * 16));
            const ll g = (ll)row * 256 + kc + c16 * 8;
            cpa16(bo + so, Bh + g);
            cpa16(bo + TBH + so, Bl + g);
        }
        cpa_commit();
    };

    auto convert_sts = [&](const float4* ar) {
#pragma unroll
        for (int j = 0; j < 8; ++j) {
            float v[8];
            const float4 p0 = ar[2 * j], p1 = ar[2 * j + 1];
            v[0] = p0.x; v[1] = p0.y; v[2] = p0.z; v[3] = p0.w;
            v[4] = p1.x; v[5] = p1.y; v[6] = p1.z; v[7] = p1.w;
            __half hh[8];
#pragma unroll
            for (int e = 0; e < 8; ++e)
                hh[e] = __float2half_rn(__expf(v[e] - mx) * inv);
            const uint32_t so = SWZ((uint32_t)(tid * 128 + j * 16));
            *(uint4*)(dsm + so) = *(const uint4*)hh;
        }
    };

    const int wid = tid >> 5, lane = tid & 31;
    const int m0w = wid * 32;
    const int lrow = lane & 15, lcol = lane >> 4;

    float acc[2][8][4];
#pragma unroll
    for (int i = 0; i < 2; i++)
#pragma unroll
        for (int j = 0; j < 8; j++)
#pragma unroll
            for (int q = 0; q < 4; q++) acc[i][j][q] = 0.f;

    load_B(0);
    float4 ar[16], ar2[16];
    const float4* scf = (const float4*)(sc + (ll)tid * 256);
#pragma unroll
    for (int i = 0; i < 16; ++i) ar[i] = scf[i];

    for (int c = 0; c < 4; ++c) {
        if (c < 3) load_B(c + 1);
        convert_sts(ar);
        if (c < 3) {
#pragma unroll
            for (int i = 0; i < 16; ++i) ar2[i] = scf[(c + 1) * 16 + i];
        }
        if (c < 3) cpa_wait<1>(); else cpa_wait<0>();
        __syncthreads();

        const uint32_t Bs_h = bBase + (c & 1) * 2 * TBH;
        const uint32_t Bs_l = Bs_h + TBH;
#pragma unroll
        for (int k16 = 0; k16 < 4; ++k16) {
            const uint32_t kb = k16 * 32;
            uint32_t ah[2][4];
#pragma unroll
            for (int i = 0; i < 2; ++i) {
                const uint32_t off = SWZ((uint32_t)((m0w + i * 16 + lrow) * 128) + kb + lcol * 16);
                ldmx4(ah[i], aH + off);
            }
            uint32_t bh[8][2], bl[8][2];
#pragma unroll
            for (int p = 0; p < 4; ++p) {
                const uint32_t off = SWZ((uint32_t)((p * 16 + lrow) * 128) + kb + lcol * 16);
                uint32_t r[4];
                ldmx4(r, Bs_h + off);
                bh[2 * p][0] = r[0]; bh[2 * p][1] = r[2];
                bh[2 * p + 1][0] = r[1]; bh[2 * p + 1][1] = r[3];
                ldmx4(r, Bs_l + off);
                bl[2 * p][0] = r[0]; bl[2 * p][1] = r[2];
                bl[2 * p + 1][0] = r[1]; bl[2 * p + 1][1] = r[3];
            }
#pragma unroll
            for (int i = 0; i < 2; ++i)
#pragma unroll
                for (int j = 0; j < 8; ++j) {
                    mma16816(acc[i][j], ah[i], bh[j]);
                    mma16816(acc[i][j], ah[i], bl[j]);
                }
        }
        __syncthreads();
#pragma unroll
        for (int i = 0; i < 16; ++i) ar[i] = ar2[i];
    }

    const int gID = lane >> 2;
    const int tc2 = (lane & 3) * 2;
#pragma unroll
    for (int i = 0; i < 2; ++i) {
        const int rA = m0w + i * 16 + gID;
        const int rB = rA + 8;
#pragma unroll
        for (int j = 0; j < 8; ++j) {
            const int col = j * 8 + tc2;
            *(uint32_t*)(Chz + (ll)rA * 1024 + col) =
                pack_h2(__float2half_rn(acc[i][j][0]), __float2half_rn(acc[i][j][1]));
            *(uint32_t*)(Chz + (ll)rB * 1024 + col) =
                pack_h2(__float2half_rn(acc[i][j][2]), __float2half_rn(acc[i][j][3]));
        }
    }
}

// ============================ host launch ============================
extern "C" void kernel_launch(void* const* d_in, const int* in_sizes, int n_in,
                              void* d_out, int out_size)
{
    const float* x  = (const float*)d_in[0];
    const float* Wq = (const float*)d_in[1];
    const float* bq = (const float*)d_in[2];
    const float* Wk = (const float*)d_in[3];
    const float* bk = (const float*)d_in[4];
    const float* Wv = (const float*)d_in[5];
    const float* bv = (const float*)d_in[6];
    const float* E  = (const float*)d_in[7];
    const float* F  = (const float*)d_in[8];
    const float* Wo = (const float*)d_in[9];
    const float* bo = (const float*)d_in[10];

    float* out    = (float*)d_out;                 // (4,4096,1024)
    float* scores = out + (ll)4 * 4096 * 1024;     // (4,16,4096,256)

    __half* P;
    cudaGetSymbolAddress((void**)&P, g_pool4);
#define PP(o) (P + (o))

    auto G1   = gemm_mma<false, true,  false, 3>;  // Q proj (3-term)
    auto G1T3 = gemm_mma<false, false, true,  3>;  // K proj transposed (3-term)
    auto G1T2 = gemm_mma<false, false, true,  2>;  // V proj transposed (2-term)
    auto G2f3 = gemm_mma<true,  false, false, 3>;  // fp32 out, 3-term (Kp partials, scores)
    auto G2f2 = gemm_mma<true,  false, false, 2>;  // fp32 out, 2-term (Vp partials, out-proj)
    const int DYN = 2 * (2 * 128 * 128 + 2 * 64 * 128);  // 98304
    const int DYNAV = 128 * 128 + 2 * 2 * 64 * 128;      // 49152
    cudaFuncSetAttribute(G1,   cudaFuncAttributeMaxDynamicSharedMemorySize, DYN);
    cudaFuncSetAttribute(G1T3, cudaFuncAttributeMaxDynamicSharedMemorySize, DYN);
    cudaFuncSetAttribute(G1T2, cudaFuncAttributeMaxDynamicSharedMemorySize, DYN);
    cudaFuncSetAttribute(G2f3, cudaFuncAttributeMaxDynamicSharedMemorySize, DYN);
    cudaFuncSetAttribute(G2f2, cudaFuncAttributeMaxDynamicSharedMemorySize, DYN);
    cudaFuncSetAttribute(av_fused, cudaFuncAttributeMaxDynamicSharedMemorySize, DYNAV);

    float* pk = (float*)PP(o_pk);
    float* pv = (float*)PP(o_pv);

    // 1) converts
    convert_split<<<(int)(NX / 4 / 256), 256>>>(x, PP(o_xh), PP(o_xl), (int)(NX / 4));
    {
        P6 p;
        p.s[0] = Wq; p.h[0] = PP(o_wqh); p.l[0] = PP(o_wql);
        p.s[1] = Wk; p.h[1] = PP(o_wkh); p.l[1] = PP(o_wkl);
        p.s[2] = Wv; p.h[2] = PP(o_wvh); p.l[2] = PP(o_wvl);
        p.s[3] = Wo; p.h[3] = PP(o_woh); p.l[3] = PP(o_wol);
        p.s[4] = E;  p.h[4] = PP(o_eh);  p.l[4] = PP(o_el);
        p.s[5] = F;  p.h[5] = PP(o_fh);  p.l[5] = PP(o_fl);
        convert6<<<dim3((int)(NW / 4 / 256), 1, 6), 256>>>(p, (int)(NW / 4));
    }

    // 2) projections: Q (3-term), K (3-term, transposed), V (2-term, transposed)
    {
        dim3 g(16, 128, 1);
        G1<<<g, 128, DYN>>>(PP(o_xh), PP(o_xl), PP(o_wqh), PP(o_wql), bq,
                            nullptr, PP(o_qh), PP(o_ql),
                            1024, 1024, 1024, 1024, 0, 0, 0, 0, 0, 0, 1, 1.0f);
        G1T3<<<g, 128, DYN>>>(PP(o_xh), PP(o_xl), PP(o_wkh), PP(o_wkl), bk,
                              nullptr, PP(o_kth), PP(o_ktl),
                              1024, 1024, 1024, 0, 0, 0, 0, 0, 0, 0, 1, 1.0f);
        G1T2<<<g, 128, DYN>>>(PP(o_xh), PP(o_xl), PP(o_wvh), PP(o_wvl), bv,
                              nullptr, PP(o_vth), PP(o_vtl),
                              1024, 1024, 1024, 0, 0, 0, 0, 0, 0, 0, 1, 1.0f);
    }

    // 3) Kp split-K=2 (3-term): partial[s][b](256x1024) = E[:,s*2048:] * Kt[b][:,s*2048:]^T
    G2f3<<<dim3(16, 2, 8), 128, DYN>>>(PP(o_eh), PP(o_el), PP(o_kth), PP(o_ktl), nullptr,
                                       pk, nullptr, nullptr,
                                       2048, 4096, 4096, 1024,
                                       0, 2048,
                                       (ll)1024 * 4096, 2048,
                                       (ll)256 * 1024, (ll)4 * 256 * 1024,
                                       2, 1.0f);
    // 4) Vp split-K=2 (2-term): partial[s][b](1024x256) = Vt[b][:,s*2048:] * F[:,s*2048:]^T
    G2f2<<<dim3(4, 8, 8), 128, DYN>>>(PP(o_vth), PP(o_vtl), PP(o_fh), PP(o_fl), nullptr,
                                      pv, nullptr, nullptr,
                                      2048, 4096, 4096, 256,
                                      (ll)1024 * 4096, 2048,
                                      0, 2048,
                                      (ll)1024 * 256, (ll)4 * 1024 * 256,
                                      2, 1.0f);
    add_split<<<(4 * 256 * 1024 / 4 + 255) / 256, 256>>>(pk, pk + (ll)4 * 256 * 1024,
                                                         PP(o_kph), PP(o_kpl), 4 * 256 * 1024 / 4);
    add_split<<<(4 * 1024 * 256 / 4 + 255) / 256, 256>>>(pv, pv + (ll)4 * 1024 * 256,
                                                         PP(o_vph), PP(o_vpl), 4 * 1024 * 256 / 4);

    // 5) scores (3-term): scores[b,h](4096x256) = Q_h * Kp_h^T / 8 -> fp32 into d_out
    G2f3<<<dim3(4, 32, 64), 128, DYN>>>(PP(o_qh), PP(o_ql), PP(o_kph), PP(o_kpl), nullptr,
                                        scores, nullptr, nullptr,
                                        64, 1024, 1024, 256,
                                        (ll)4096 * 1024, 64, (ll)256 * 1024, 64,
                                        (ll)16 * 4096 * 256, (ll)4096 * 256, 16, 0.125f);

    // 6) softmax stats
    softmax_stats<<<(4 * 16 * 4096) / 4, 128>>>(scores, (float2*)PP(o_st));

    // 7) fused softmax+AV (2-term, outh hi only)
    av_fused<<<dim3(1, 32, 64), 128, DYNAV>>>(scores, (const float2*)PP(o_st),
                                              PP(o_vph), PP(o_vpl),
                                              PP(o_ohh));

    // 8) out-proj (2-term): out = fp16(outh) * Wo^T + bo
    G2f2<<<dim3(16, 128, 1), 128, DYN>>>(PP(o_ohh), PP(o_ohh), PP(o_woh), PP(o_wol), bo,
                                         out, nullptr, nullptr,
                                         1024, 1024, 1024, 1024,
                                         0, 0, 0, 0, 0, 0, 1, 1.0f);
#undef PP
}